// round 14
// baseline (speedup 1.0000x reference)
#include <cuda_runtime.h>
#include <cuda_fp16.h>
#include <cstdint>
#include <cstddef>

#define B_DIM   64
#define S_DIM   2048
#define H_DIM   1024
#define E_DIM   2048                  // 2H (contraction dim)
#define M_TOTAL (B_DIM * S_DIM)       // 131072

// ---------------- device scratch ----------------
__device__ __half g_enc16[(size_t)M_TOTAL * E_DIM];   // compacted fp16 encoder rows
__device__ __half g_wt[(size_t)H_DIM * E_DIM];        // W_s^T : [n][k] fp16
__device__ float  g_decf[B_DIM * H_DIM];
__device__ float  g_epart[8 * M_TOTAL];               // 8 N-tiles of 128 (compacted rows)
__device__ int    g_sidx[M_TOTAL];                    // compacted row -> original s
__device__ int    g_count[B_DIM];                     // unmasked count per batch
__device__ float  g_attnc[M_TOTAL];                   // compacted attention weights

#define SWZ(x) ((x) ^ (((x) >> 3) & 0x70))

// ---------------- K0: per-batch mask compaction (ordered scan) ----------------
__global__ void compact_kernel(const int* __restrict__ mask) {
    const int b = blockIdx.x, tid = threadIdx.x;
    const int lane = tid & 31, wid = tid >> 5;
    __shared__ int wsum[8];
    int m[8], loc[8];
    int t = 0;
    #pragma unroll
    for (int i = 0; i < 8; i++) {
        m[i] = mask[b * S_DIM + tid * 8 + i];
        loc[i] = t;
        t += (m[i] != 0);
    }
    int ws = t;
    #pragma unroll
    for (int off = 1; off < 32; off <<= 1) {
        int y = __shfl_up_sync(0xffffffffu, ws, off);
        if (lane >= off) ws += y;
    }
    if (lane == 31) wsum[wid] = ws;
    __syncthreads();
    if (wid == 0) {
        int v = (lane < 8) ? wsum[lane] : 0;
        #pragma unroll
        for (int off = 1; off < 8; off <<= 1) {
            int y = __shfl_up_sync(0xffffffffu, v, off);
            if (lane >= off) v += y;
        }
        if (lane < 8) wsum[lane] = v;
    }
    __syncthreads();
    int base = ws - t + ((wid > 0) ? wsum[wid - 1] : 0);
    #pragma unroll
    for (int i = 0; i < 8; i++)
        if (m[i]) g_sidx[b * S_DIM + base + loc[i]] = tid * 8 + i;
    if (tid == 255) g_count[b] = base + t;
}

// ---------------- K1: gather + fp32->fp16 convert of unmasked rows ----------------
__global__ void gather_kernel(const float* __restrict__ enc) {
    const int b = blockIdx.y, j = blockIdx.x, tid = threadIdx.x;
    const int cnt = g_count[b];
    const int cntP = (cnt + 63) & ~63;
    if (j >= cntP) return;
    __half2* dst = reinterpret_cast<__half2*>(g_enc16 + ((size_t)b * S_DIM + j) * E_DIM);
    if (j < cnt) {
        const int s = g_sidx[b * S_DIM + j];
        const float4* src = reinterpret_cast<const float4*>(enc) +
                            ((size_t)b * S_DIM + s) * (E_DIM / 4);
        #pragma unroll
        for (int i = 0; i < 2; i++) {
            float4 v = src[tid + i * 256];
            dst[2 * (tid + i * 256)]     = __floats2half2_rn(v.x, v.y);
            dst[2 * (tid + i * 256) + 1] = __floats2half2_rn(v.z, v.w);
        }
    } else {
        uint4 z = make_uint4(0, 0, 0, 0);
        reinterpret_cast<uint4*>(dst)[tid] = z;
    }
}

// ---------------- K2: W_s [k=2048][n=1024] -> g_wt[n][k] fp16 ----------------
__global__ void wt_kernel(const float* __restrict__ Ws) {
    __shared__ float t[32][33];
    int n0 = blockIdx.x * 32, k0 = blockIdx.y * 32;
    int tx = threadIdx.x, ty = threadIdx.y;  // 32 x 8
    #pragma unroll
    for (int i = 0; i < 32; i += 8)
        t[ty + i][tx] = Ws[(size_t)(k0 + ty + i) * H_DIM + n0 + tx];
    __syncthreads();
    #pragma unroll
    for (int i = 0; i < 32; i += 8)
        g_wt[(size_t)(n0 + ty + i) * E_DIM + k0 + tx] = __float2half(t[tx][ty + i]);
}

// ---------------- K3: dec_f = decoder_hidden @ W_h (8 accumulator chains) --------
__global__ void decf_kernel(const float* __restrict__ dh, const float* __restrict__ Wh) {
    __shared__ float dsm[H_DIM];
    int b = blockIdx.x >> 2;
    int n = (blockIdx.x & 3) * 256 + threadIdx.x;
    for (int i = threadIdx.x; i < H_DIM; i += 256) dsm[i] = dh[b * H_DIM + i];
    __syncthreads();
    float acc[8];
    #pragma unroll
    for (int j = 0; j < 8; j++) acc[j] = 0.f;
    #pragma unroll 2
    for (int k0 = 0; k0 < H_DIM; k0 += 8) {
        #pragma unroll
        for (int j = 0; j < 8; j++)
            acc[j] = fmaf(dsm[k0 + j], Wh[(size_t)(k0 + j) * H_DIM + n], acc[j]);
    }
    float s = ((acc[0] + acc[1]) + (acc[2] + acc[3])) +
              ((acc[4] + acc[5]) + (acc[6] + acc[7]));
    g_decf[b * H_DIM + n] = s;
}

// ---------------- K4: fused energy GEMM (round-10 proven code, unchanged) --------
// CTA: 128 threads (4 warps), tile M=64 x N=128, K chunks of 64.
// 3-stage cp.async pipeline, 24KB/stage, SW128 swizzle, 3 CTAs/SM.
static constexpr int STAGE_BYTES = 24576;
static constexpr int DYN_SMEM = 3 * STAGE_BYTES;     // 73728

__global__ __launch_bounds__(128, 3)
void energy_kernel(const float* __restrict__ v) {
    const int nTile = blockIdx.x & 7;
    const int mTile = blockIdx.x >> 3;
    const int row0 = mTile * 64;                 // = b*2048 + local
    const int b = mTile >> 5;
    const int local = row0 & (S_DIM - 1);
    if (local >= g_count[b]) return;             // compaction early exit

    extern __shared__ char dsm[];
    __shared__ float dec_sm[128], v_sm[128], e2[2][64];

    uint32_t sbase;
    asm("{ .reg .u64 t; cvta.to.shared.u64 t, %1; cvt.u32.u64 %0, t; }"
        : "=r"(sbase) : "l"(dsm));

    const int tid = threadIdx.x;
    const int lane = tid & 31, wid = tid >> 5;
    const int wm = wid & 1, wn = wid >> 1;       // warp tile: rows wm*32, cols wn*64
    const int n0 = nTile * 128;

    dec_sm[tid] = g_decf[b * H_DIM + n0 + tid];
    v_sm[tid]   = v[n0 + tid];

    const char* aG = reinterpret_cast<const char*>(g_enc16 + (size_t)row0 * E_DIM);
    const char* bG = reinterpret_cast<const char*>(g_wt + (size_t)n0 * E_DIM);

    // ---- precompute cp.async offsets (12 per thread: 4 A, 8 B) ----
    uint32_t cp_dst[12];
    uint32_t cp_src[12];
    #pragma unroll
    for (int it = 0; it < 12; it++) {
        int t = tid + it * 128;
        if (it < 4) {                        // A: 64 rows x 8 x 16B
            int r = t >> 3, c8 = t & 7;
            cp_src[it] = (uint32_t)(r * (E_DIM * 2) + c8 * 16);
            cp_dst[it] = SWZ((uint32_t)(r * 128 + c8 * 16));
        } else {                             // B: 128 rows x 8 x 16B
            int idx = t - 512;
            int r = idx >> 3, c8 = idx & 7;
            cp_src[it] = (uint32_t)(r * (E_DIM * 2) + c8 * 16);
            cp_dst[it] = 8192u + SWZ((uint32_t)(r * 128 + c8 * 16));
        }
    }

    // ---- precompute ldmatrix offsets within a stage ----
    uint32_t lmA[2][4], lmB[4][4];
    #pragma unroll
    for (int kk = 0; kk < 4; kk++) {
        int colb = kk * 32 + ((lane >> 4) << 4);
        #pragma unroll
        for (int mf = 0; mf < 2; mf++) {
            int row = wm * 32 + mf * 16 + (lane & 15);
            lmA[mf][kk] = SWZ((uint32_t)(row * 128 + colb));
        }
        #pragma unroll
        for (int ng = 0; ng < 4; ng++) {
            int nrow = wn * 64 + ng * 16 + (lane & 15);
            lmB[ng][kk] = 8192u + SWZ((uint32_t)(nrow * 128 + colb));
        }
    }

    auto load_chunk = [&](int c, int s) {
        const uint32_t base = sbase + (uint32_t)s * STAGE_BYTES;
        const uint32_t koff = (uint32_t)c * 128u;
        #pragma unroll
        for (int it = 0; it < 12; ++it) {
            const char* g = ((it < 4) ? aG : bG) + cp_src[it] + koff;
            uint32_t dst = base + cp_dst[it];
            asm volatile("cp.async.cg.shared.global [%0], [%1], 16;" :: "r"(dst), "l"(g));
        }
        asm volatile("cp.async.commit_group;" ::: "memory");
    };

    float acc[2][8][4];
    #pragma unroll
    for (int i = 0; i < 2; i++)
        #pragma unroll
        for (int j = 0; j < 8; j++)
            #pragma unroll
            for (int q = 0; q < 4; q++) acc[i][j][q] = 0.f;

    load_chunk(0, 0);
    load_chunk(1, 1);

    const int NC = E_DIM / 64;               // 32
    #pragma unroll 1
    for (int c = 0; c < NC; c++) {
        if (c < NC - 1) asm volatile("cp.async.wait_group 1;" ::: "memory");
        else            asm volatile("cp.async.wait_group 0;" ::: "memory");
        __syncthreads();
        if (c + 2 < NC) load_chunk(c + 2, (c + 2) % 3);

        const uint32_t stage = sbase + (uint32_t)(c % 3) * STAGE_BYTES;

        #pragma unroll
        for (int kk = 0; kk < 4; kk++) {
            uint32_t af[2][4], bf[4][4];
            #pragma unroll
            for (int mf = 0; mf < 2; mf++) {
                uint32_t a = stage + lmA[mf][kk];
                asm volatile("ldmatrix.sync.aligned.m8n8.x4.shared.b16 {%0,%1,%2,%3}, [%4];"
                             : "=r"(af[mf][0]), "=r"(af[mf][1]), "=r"(af[mf][2]), "=r"(af[mf][3])
                             : "r"(a));
            }
            #pragma unroll
            for (int ng = 0; ng < 4; ng++) {
                uint32_t a = stage + lmB[ng][kk];
                asm volatile("ldmatrix.sync.aligned.m8n8.x4.shared.b16 {%0,%1,%2,%3}, [%4];"
                             : "=r"(bf[ng][0]), "=r"(bf[ng][1]), "=r"(bf[ng][2]), "=r"(bf[ng][3])
                             : "r"(a));
            }
            #pragma unroll
            for (int mf = 0; mf < 2; mf++)
                #pragma unroll
                for (int nf = 0; nf < 8; nf++) {
                    int ng = nf >> 1, hi = nf & 1;
                    asm volatile(
                        "mma.sync.aligned.m16n8k16.row.col.f32.f16.f16.f32 "
                        "{%0,%1,%2,%3}, {%4,%5,%6,%7}, {%8,%9}, {%0,%1,%2,%3};"
                        : "+f"(acc[mf][nf][0]), "+f"(acc[mf][nf][1]),
                          "+f"(acc[mf][nf][2]), "+f"(acc[mf][nf][3])
                        : "r"(af[mf][0]), "r"(af[mf][1]), "r"(af[mf][2]), "r"(af[mf][3]),
                          "r"(bf[ng][hi]), "r"(bf[ng][hi + 2]));
                }
        }
    }

    // ---- epilogue: tanh + v-dot, per-warp reduce over its 64 cols ----
    float rsum[2][2];
    rsum[0][0] = rsum[0][1] = rsum[1][0] = rsum[1][1] = 0.f;
    #pragma unroll
    for (int mf = 0; mf < 2; mf++)
        #pragma unroll
        for (int nf = 0; nf < 8; nf++)
            #pragma unroll
            for (int rg = 0; rg < 4; rg++) {
                int col = wn * 64 + nf * 8 + (lane & 3) * 2 + (rg & 1);
                float x = acc[mf][nf][rg] + dec_sm[col];
                float ex = __expf(x + x);
                float th = 1.0f - __fdividef(2.0f, ex + 1.0f);
                rsum[mf][rg >> 1] = fmaf(th, v_sm[col], rsum[mf][rg >> 1]);
            }
    #pragma unroll
    for (int mf = 0; mf < 2; mf++)
        #pragma unroll
        for (int rh = 0; rh < 2; rh++) {
            float x = rsum[mf][rh];
            x += __shfl_xor_sync(0xffffffffu, x, 1);
            x += __shfl_xor_sync(0xffffffffu, x, 2);
            if ((lane & 3) == 0)
                e2[wn][wm * 32 + mf * 16 + rh * 8 + (lane >> 2)] = x;
        }
    __syncthreads();
    if (tid < 64)
        g_epart[(size_t)nTile * M_TOTAL + row0 + tid] = e2[0][tid] + e2[1][tid];
}

// ---------------- K5: softmax over compacted rows, scatter to attn ----------------
__global__ void softmax_kernel(float* __restrict__ out) {
    __shared__ float red[256];
    const int b = blockIdx.x, tid = threadIdx.x;
    const int cnt = g_count[b];
    float* attn = out + B_DIM * E_DIM;
    for (int j = tid; j < S_DIM; j += 256) attn[b * S_DIM + j] = 0.f;  // masked -> 0

    float e[8];
    float m = -1e30f;
    #pragma unroll
    for (int jj = 0; jj < 8; jj++) {
        int j = jj * 256 + tid;
        float x = -1e30f;
        if (j < cnt) {
            x = 0.f;
            #pragma unroll
            for (int t = 0; t < 8; t++)
                x += g_epart[(size_t)t * M_TOTAL + b * S_DIM + j];
        }
        e[jj] = x;
        m = fmaxf(m, x);
    }
    red[tid] = m; __syncthreads();
    for (int st = 128; st > 0; st >>= 1) {
        if (tid < st) red[tid] = fmaxf(red[tid], red[tid + st]);
        __syncthreads();
    }
    const float mx = red[0];
    __syncthreads();
    float sl = 0.f;
    #pragma unroll
    for (int jj = 0; jj < 8; jj++) {
        int j = jj * 256 + tid;
        float w = (j < cnt) ? __expf(e[jj] - mx) : 0.f;
        e[jj] = w;
        sl += w;
    }
    red[tid] = sl; __syncthreads();
    for (int st = 128; st > 0; st >>= 1) {
        if (tid < st) red[tid] += red[tid + st];
        __syncthreads();
    }
    const float inv = 1.0f / red[0];
    #pragma unroll
    for (int jj = 0; jj < 8; jj++) {
        int j = jj * 256 + tid;
        if (j < cnt) {
            float w = e[jj] * inv;
            attn[b * S_DIM + g_sidx[b * S_DIM + j]] = w;
            g_attnc[b * S_DIM + j] = w;
        }
    }
}

// ---------------- K6: context from compacted rows/weights ----------------
__global__ void context_kernel(float* __restrict__ out) {
    __shared__ float attn_sm[S_DIM];
    const int b = blockIdx.x >> 2;
    const int ec = blockIdx.x & 3;
    const int tid = threadIdx.x;
    const int cnt = g_count[b];
    const int cntP = (cnt + 63) & ~63;
    for (int i = tid; i < cntP; i += 256)
        attn_sm[i] = (i < cnt) ? g_attnc[b * S_DIM + i] : 0.f;
    __syncthreads();
    const int e0 = ec * 512 + tid * 2;
    const __half2* ep = reinterpret_cast<const __half2*>(
        g_enc16 + (size_t)b * S_DIM * E_DIM) + (e0 >> 1);
    float ax = 0.f, ay = 0.f;
    for (int s0 = 0; s0 < cntP; s0 += 8) {
        #pragma unroll
        for (int j = 0; j < 8; j++) {
            float2 f = __half22float2(ep[(size_t)(s0 + j) * (E_DIM / 2)]);
            float w = attn_sm[s0 + j];
            ax = fmaf(w, f.x, ax);
            ay = fmaf(w, f.y, ay);
        }
    }
    out[b * E_DIM + e0]     = ax;
    out[b * E_DIM + e0 + 1] = ay;
}

// ---------------- launch ----------------
extern "C" void kernel_launch(void* const* d_in, const int* in_sizes, int n_in,
                              void* d_out, int out_size) {
    const float* dh   = (const float*)d_in[0];
    const float* enc  = (const float*)d_in[1];
    const int*   mask = (const int*)d_in[2];
    const float* Wh   = (const float*)d_in[3];
    const float* Ws   = (const float*)d_in[4];
    const float* v    = (const float*)d_in[5];
    float* out = (float*)d_out;

    compact_kernel<<<B_DIM, 256>>>(mask);
    gather_kernel<<<dim3(S_DIM, B_DIM), 256>>>(enc);
    wt_kernel<<<dim3(32, 64), dim3(32, 8)>>>(Ws);
    decf_kernel<<<256, 256>>>(dh, Wh);

    cudaFuncSetAttribute(energy_kernel, cudaFuncAttributeMaxDynamicSharedMemorySize, DYN_SMEM);
    energy_kernel<<<16384, 128, DYN_SMEM>>>(v);

    softmax_kernel<<<64, 256>>>(out);
    context_kernel<<<256, 256>>>(out);
}

// round 15
// speedup vs baseline: 1.0498x; 1.0498x over previous
#include <cuda_runtime.h>
#include <cuda_fp16.h>
#include <cstdint>
#include <cstddef>

#define B_DIM   64
#define S_DIM   2048
#define H_DIM   1024
#define E_DIM   2048                  // 2H (contraction dim)
#define M_TOTAL (B_DIM * S_DIM)      // 131072
#define KSPLIT  8

// ---------------- device scratch ----------------
__device__ __half g_enc16[(size_t)M_TOTAL * E_DIM];   // compacted fp16 encoder rows
__device__ __half g_wt[(size_t)H_DIM * E_DIM];        // W_s^T : [n][k] fp16
__device__ float  g_decf_part[KSPLIT * B_DIM * H_DIM];// k-split partials of dec_f
__device__ float  g_epart[8 * M_TOTAL];               // 8 N-tiles of 128 (compacted rows)
__device__ int    g_sidx[M_TOTAL];                    // compacted row -> original s
__device__ int    g_count[B_DIM];                     // unmasked count per batch
__device__ float  g_attnc[M_TOTAL];                   // compacted attention weights

#define SWZ(x) ((x) ^ (((x) >> 3) & 0x70))

// ---------------- K0: per-batch mask compaction (ordered scan) ----------------
__global__ void compact_kernel(const int* __restrict__ mask) {
    const int b = blockIdx.x, tid = threadIdx.x;
    const int lane = tid & 31, wid = tid >> 5;
    __shared__ int wsum[8];
    int m[8], loc[8];
    int t = 0;
    #pragma unroll
    for (int i = 0; i < 8; i++) {
        m[i] = mask[b * S_DIM + tid * 8 + i];
        loc[i] = t;
        t += (m[i] != 0);
    }
    int ws = t;
    #pragma unroll
    for (int off = 1; off < 32; off <<= 1) {
        int y = __shfl_up_sync(0xffffffffu, ws, off);
        if (lane >= off) ws += y;
    }
    if (lane == 31) wsum[wid] = ws;
    __syncthreads();
    if (wid == 0) {
        int v = (lane < 8) ? wsum[lane] : 0;
        #pragma unroll
        for (int off = 1; off < 8; off <<= 1) {
            int y = __shfl_up_sync(0xffffffffu, v, off);
            if (lane >= off) v += y;
        }
        if (lane < 8) wsum[lane] = v;
    }
    __syncthreads();
    int base = ws - t + ((wid > 0) ? wsum[wid - 1] : 0);
    #pragma unroll
    for (int i = 0; i < 8; i++)
        if (m[i]) g_sidx[b * S_DIM + base + loc[i]] = tid * 8 + i;
    if (tid == 255) g_count[b] = base + t;
}

// ---------------- K1: gather + fp32->fp16 convert of unmasked rows ----------------
__global__ void gather_kernel(const float* __restrict__ enc) {
    const int b = blockIdx.y, j = blockIdx.x, tid = threadIdx.x;
    const int cnt = g_count[b];
    const int cntP = (cnt + 63) & ~63;
    if (j >= cntP) return;
    __half2* dst = reinterpret_cast<__half2*>(g_enc16 + ((size_t)b * S_DIM + j) * E_DIM);
    if (j < cnt) {
        const int s = g_sidx[b * S_DIM + j];
        const float4* src = reinterpret_cast<const float4*>(enc) +
                            ((size_t)b * S_DIM + s) * (E_DIM / 4);
        #pragma unroll
        for (int i = 0; i < 2; i++) {
            float4 v = src[tid + i * 256];
            dst[2 * (tid + i * 256)]     = __floats2half2_rn(v.x, v.y);
            dst[2 * (tid + i * 256) + 1] = __floats2half2_rn(v.z, v.w);
        }
    } else {
        uint4 z = make_uint4(0, 0, 0, 0);
        reinterpret_cast<uint4*>(dst)[tid] = z;
    }
}

// ---------------- K2: W_s [k=2048][n=1024] -> g_wt[n][k] fp16 ----------------
__global__ void wt_kernel(const float* __restrict__ Ws) {
    __shared__ float t[32][33];
    int n0 = blockIdx.x * 32, k0 = blockIdx.y * 32;
    int tx = threadIdx.x, ty = threadIdx.y;  // 32 x 8
    #pragma unroll
    for (int i = 0; i < 32; i += 8)
        t[ty + i][tx] = Ws[(size_t)(k0 + ty + i) * H_DIM + n0 + tx];
    __syncthreads();
    #pragma unroll
    for (int i = 0; i < 32; i += 8)
        g_wt[(size_t)(n0 + ty + i) * E_DIM + k0 + tx] = __float2half(t[tx][ty + i]);
}

// ---------------- K3: dec_f partials, k-split x8 (deterministic, no atomics) -----
// grid (256, KSPLIT): blockIdx.x -> (b, n-chunk), blockIdx.y -> k range of 128.
__global__ __launch_bounds__(256)
void decf_kernel(const float* __restrict__ dh, const float* __restrict__ Wh) {
    __shared__ float dsm[H_DIM / KSPLIT];            // 128 floats
    const int b = blockIdx.x >> 2;
    const int n = (blockIdx.x & 3) * 256 + threadIdx.x;
    const int ks = blockIdx.y;
    const int kbase = ks * (H_DIM / KSPLIT);
    if (threadIdx.x < H_DIM / KSPLIT)
        dsm[threadIdx.x] = dh[b * H_DIM + kbase + threadIdx.x];
    __syncthreads();
    float acc[8];
    #pragma unroll
    for (int j = 0; j < 8; j++) acc[j] = 0.f;
    #pragma unroll 2
    for (int k0 = 0; k0 < H_DIM / KSPLIT; k0 += 8) {
        #pragma unroll
        for (int j = 0; j < 8; j++)
            acc[j] = fmaf(dsm[k0 + j],
                          __ldg(&Wh[(size_t)(kbase + k0 + j) * H_DIM + n]), acc[j]);
    }
    float s = ((acc[0] + acc[1]) + (acc[2] + acc[3])) +
              ((acc[4] + acc[5]) + (acc[6] + acc[7]));
    g_decf_part[ks * (B_DIM * H_DIM) + b * H_DIM + n] = s;
}

// ---------------- K4: fused energy GEMM (round-10 proven mainloop, unchanged) ----
// CTA: 128 threads (4 warps), tile M=64 x N=128, K chunks of 64.
// 3-stage cp.async pipeline, 24KB/stage, SW128 swizzle, 3 CTAs/SM.
static constexpr int STAGE_BYTES = 24576;
static constexpr int DYN_SMEM = 3 * STAGE_BYTES;     // 73728

__global__ __launch_bounds__(128, 3)
void energy_kernel(const float* __restrict__ v) {
    const int nTile = blockIdx.x & 7;
    const int mTile = blockIdx.x >> 3;
    const int row0 = mTile * 64;                 // = b*2048 + local
    const int b = mTile >> 5;
    const int local = row0 & (S_DIM - 1);
    if (local >= g_count[b]) return;             // compaction early exit

    extern __shared__ char dsm[];
    __shared__ float dec_sm[128], v_sm[128], e2[2][64];

    uint32_t sbase;
    asm("{ .reg .u64 t; cvta.to.shared.u64 t, %1; cvt.u32.u64 %0, t; }"
        : "=r"(sbase) : "l"(dsm));

    const int tid = threadIdx.x;
    const int lane = tid & 31, wid = tid >> 5;
    const int wm = wid & 1, wn = wid >> 1;       // warp tile: rows wm*32, cols wn*64
    const int n0 = nTile * 128;

    {   // dec_f = sum of KSPLIT partials (deterministic fixed order)
        float s = 0.f;
        #pragma unroll
        for (int ks = 0; ks < KSPLIT; ks++)
            s += g_decf_part[ks * (B_DIM * H_DIM) + b * H_DIM + n0 + tid];
        dec_sm[tid] = s;
    }
    v_sm[tid] = v[n0 + tid];

    const char* aG = reinterpret_cast<const char*>(g_enc16 + (size_t)row0 * E_DIM);
    const char* bG = reinterpret_cast<const char*>(g_wt + (size_t)n0 * E_DIM);

    // ---- precompute cp.async offsets (12 per thread: 4 A, 8 B) ----
    uint32_t cp_dst[12];
    uint32_t cp_src[12];
    #pragma unroll
    for (int it = 0; it < 12; it++) {
        int t = tid + it * 128;
        if (it < 4) {                        // A: 64 rows x 8 x 16B
            int r = t >> 3, c8 = t & 7;
            cp_src[it] = (uint32_t)(r * (E_DIM * 2) + c8 * 16);
            cp_dst[it] = SWZ((uint32_t)(r * 128 + c8 * 16));
        } else {                             // B: 128 rows x 8 x 16B
            int idx = t - 512;
            int r = idx >> 3, c8 = idx & 7;
            cp_src[it] = (uint32_t)(r * (E_DIM * 2) + c8 * 16);
            cp_dst[it] = 8192u + SWZ((uint32_t)(r * 128 + c8 * 16));
        }
    }

    // ---- precompute ldmatrix offsets within a stage ----
    uint32_t lmA[2][4], lmB[4][4];
    #pragma unroll
    for (int kk = 0; kk < 4; kk++) {
        int colb = kk * 32 + ((lane >> 4) << 4);
        #pragma unroll
        for (int mf = 0; mf < 2; mf++) {
            int row = wm * 32 + mf * 16 + (lane & 15);
            lmA[mf][kk] = SWZ((uint32_t)(row * 128 + colb));
        }
        #pragma unroll
        for (int ng = 0; ng < 4; ng++) {
            int nrow = wn * 64 + ng * 16 + (lane & 15);
            lmB[ng][kk] = 8192u + SWZ((uint32_t)(nrow * 128 + colb));
        }
    }

    auto load_chunk = [&](int c, int s) {
        const uint32_t base = sbase + (uint32_t)s * STAGE_BYTES;
        const uint32_t koff = (uint32_t)c * 128u;
        #pragma unroll
        for (int it = 0; it < 12; ++it) {
            const char* g = ((it < 4) ? aG : bG) + cp_src[it] + koff;
            uint32_t dst = base + cp_dst[it];
            asm volatile("cp.async.cg.shared.global [%0], [%1], 16;" :: "r"(dst), "l"(g));
        }
        asm volatile("cp.async.commit_group;" ::: "memory");
    };

    float acc[2][8][4];
    #pragma unroll
    for (int i = 0; i < 2; i++)
        #pragma unroll
        for (int j = 0; j < 8; j++)
            #pragma unroll
            for (int q = 0; q < 4; q++) acc[i][j][q] = 0.f;

    load_chunk(0, 0);
    load_chunk(1, 1);

    const int NC = E_DIM / 64;               // 32
    #pragma unroll 1
    for (int c = 0; c < NC; c++) {
        if (c < NC - 1) asm volatile("cp.async.wait_group 1;" ::: "memory");
        else            asm volatile("cp.async.wait_group 0;" ::: "memory");
        __syncthreads();
        if (c + 2 < NC) load_chunk(c + 2, (c + 2) % 3);

        const uint32_t stage = sbase + (uint32_t)(c % 3) * STAGE_BYTES;

        #pragma unroll
        for (int kk = 0; kk < 4; kk++) {
            uint32_t af[2][4], bf[4][4];
            #pragma unroll
            for (int mf = 0; mf < 2; mf++) {
                uint32_t a = stage + lmA[mf][kk];
                asm volatile("ldmatrix.sync.aligned.m8n8.x4.shared.b16 {%0,%1,%2,%3}, [%4];"
                             : "=r"(af[mf][0]), "=r"(af[mf][1]), "=r"(af[mf][2]), "=r"(af[mf][3])
                             : "r"(a));
            }
            #pragma unroll
            for (int ng = 0; ng < 4; ng++) {
                uint32_t a = stage + lmB[ng][kk];
                asm volatile("ldmatrix.sync.aligned.m8n8.x4.shared.b16 {%0,%1,%2,%3}, [%4];"
                             : "=r"(bf[ng][0]), "=r"(bf[ng][1]), "=r"(bf[ng][2]), "=r"(bf[ng][3])
                             : "r"(a));
            }
            #pragma unroll
            for (int mf = 0; mf < 2; mf++)
                #pragma unroll
                for (int nf = 0; nf < 8; nf++) {
                    int ng = nf >> 1, hi = nf & 1;
                    asm volatile(
                        "mma.sync.aligned.m16n8k16.row.col.f32.f16.f16.f32 "
                        "{%0,%1,%2,%3}, {%4,%5,%6,%7}, {%8,%9}, {%0,%1,%2,%3};"
                        : "+f"(acc[mf][nf][0]), "+f"(acc[mf][nf][1]),
                          "+f"(acc[mf][nf][2]), "+f"(acc[mf][nf][3])
                        : "r"(af[mf][0]), "r"(af[mf][1]), "r"(af[mf][2]), "r"(af[mf][3]),
                          "r"(bf[ng][hi]), "r"(bf[ng][hi + 2]));
                }
        }
    }

    // ---- epilogue: tanh + v-dot, per-warp reduce over its 64 cols ----
    float rsum[2][2];
    rsum[0][0] = rsum[0][1] = rsum[1][0] = rsum[1][1] = 0.f;
    #pragma unroll
    for (int mf = 0; mf < 2; mf++)
        #pragma unroll
        for (int nf = 0; nf < 8; nf++)
            #pragma unroll
            for (int rg = 0; rg < 4; rg++) {
                int col = wn * 64 + nf * 8 + (lane & 3) * 2 + (rg & 1);
                float x = acc[mf][nf][rg] + dec_sm[col];
                float ex = __expf(x + x);
                float th = 1.0f - __fdividef(2.0f, ex + 1.0f);
                rsum[mf][rg >> 1] = fmaf(th, v_sm[col], rsum[mf][rg >> 1]);
            }
    #pragma unroll
    for (int mf = 0; mf < 2; mf++)
        #pragma unroll
        for (int rh = 0; rh < 2; rh++) {
            float x = rsum[mf][rh];
            x += __shfl_xor_sync(0xffffffffu, x, 1);
            x += __shfl_xor_sync(0xffffffffu, x, 2);
            if ((lane & 3) == 0)
                e2[wn][wm * 32 + mf * 16 + rh * 8 + (lane >> 2)] = x;
        }
    __syncthreads();
    if (tid < 64)
        g_epart[(size_t)nTile * M_TOTAL + row0 + tid] = e2[0][tid] + e2[1][tid];
}

// ---------------- K5: softmax over compacted rows, scatter to attn ----------------
__global__ void softmax_kernel(float* __restrict__ out) {
    __shared__ float red[256];
    const int b = blockIdx.x, tid = threadIdx.x;
    const int cnt = g_count[b];
    float* attn = out + B_DIM * E_DIM;
    for (int j = tid; j < S_DIM; j += 256) attn[b * S_DIM + j] = 0.f;  // masked -> 0

    float e[8];
    float m = -1e30f;
    #pragma unroll
    for (int jj = 0; jj < 8; jj++) {
        int j = jj * 256 + tid;
        float x = -1e30f;
        if (j < cnt) {
            x = 0.f;
            #pragma unroll
            for (int t = 0; t < 8; t++)
                x += g_epart[(size_t)t * M_TOTAL + b * S_DIM + j];
        }
        e[jj] = x;
        m = fmaxf(m, x);
    }
    red[tid] = m; __syncthreads();
    for (int st = 128; st > 0; st >>= 1) {
        if (tid < st) red[tid] = fmaxf(red[tid], red[tid + st]);
        __syncthreads();
    }
    const float mx = red[0];
    __syncthreads();
    float sl = 0.f;
    #pragma unroll
    for (int jj = 0; jj < 8; jj++) {
        int j = jj * 256 + tid;
        float w = (j < cnt) ? __expf(e[jj] - mx) : 0.f;
        e[jj] = w;
        sl += w;
    }
    red[tid] = sl; __syncthreads();
    for (int st = 128; st > 0; st >>= 1) {
        if (tid < st) red[tid] += red[tid + st];
        __syncthreads();
    }
    const float inv = 1.0f / red[0];
    #pragma unroll
    for (int jj = 0; jj < 8; jj++) {
        int j = jj * 256 + tid;
        if (j < cnt) {
            float w = e[jj] * inv;
            attn[b * S_DIM + g_sidx[b * S_DIM + j]] = w;
            g_attnc[b * S_DIM + j] = w;
        }
    }
}

// ---------------- K6: context from compacted rows/weights ----------------
__global__ void context_kernel(float* __restrict__ out) {
    __shared__ float attn_sm[S_DIM];
    const int b = blockIdx.x >> 2;
    const int ec = blockIdx.x & 3;
    const int tid = threadIdx.x;
    const int cnt = g_count[b];
    const int cntP = (cnt + 63) & ~63;
    for (int i = tid; i < cntP; i += 256)
        attn_sm[i] = (i < cnt) ? g_attnc[b * S_DIM + i] : 0.f;
    __syncthreads();
    const int e0 = ec * 512 + tid * 2;
    const __half2* ep = reinterpret_cast<const __half2*>(
        g_enc16 + (size_t)b * S_DIM * E_DIM) + (e0 >> 1);
    float ax = 0.f, ay = 0.f;
    for (int s0 = 0; s0 < cntP; s0 += 8) {
        #pragma unroll
        for (int j = 0; j < 8; j++) {
            float2 f = __half22float2(ep[(size_t)(s0 + j) * (E_DIM / 2)]);
            float w = attn_sm[s0 + j];
            ax = fmaf(w, f.x, ax);
            ay = fmaf(w, f.y, ay);
        }
    }
    out[b * E_DIM + e0]     = ax;
    out[b * E_DIM + e0 + 1] = ay;
}

// ---------------- launch ----------------
extern "C" void kernel_launch(void* const* d_in, const int* in_sizes, int n_in,
                              void* d_out, int out_size) {
    const float* dh   = (const float*)d_in[0];
    const float* enc  = (const float*)d_in[1];
    const int*   mask = (const int*)d_in[2];
    const float* Wh   = (const float*)d_in[3];
    const float* Ws   = (const float*)d_in[4];
    const float* v    = (const float*)d_in[5];
    float* out = (float*)d_out;

    compact_kernel<<<B_DIM, 256>>>(mask);
    gather_kernel<<<dim3(S_DIM, B_DIM), 256>>>(enc);
    wt_kernel<<<dim3(32, 64), dim3(32, 8)>>>(Ws);
    decf_kernel<<<dim3(256, KSPLIT), 256>>>(dh, Wh);

    cudaFuncSetAttribute(energy_kernel, cudaFuncAttributeMaxDynamicSharedMemorySize, DYN_SMEM);
    energy_kernel<<<16384, 128, DYN_SMEM>>>(v);

    softmax_kernel<<<64, 256>>>(out);
    context_kernel<<<256, 256>>>(out);
}

// round 16
// speedup vs baseline: 1.0692x; 1.0186x over previous
#include <cuda_runtime.h>
#include <cuda_fp16.h>
#include <cstdint>
#include <cstddef>

#define B_DIM   64
#define S_DIM   2048
#define H_DIM   1024
#define E_DIM   2048                  // 2H (contraction dim)
#define M_TOTAL (B_DIM * S_DIM)      // 131072
#define KSPLIT  8

// ---------------- device scratch ----------------
__device__ __half g_enc16[(size_t)M_TOTAL * E_DIM];   // compacted fp16 encoder rows
__device__ __half g_wt[(size_t)H_DIM * E_DIM];        // W_s^T : [n][k] fp16
__device__ float  g_decf_part[KSPLIT * B_DIM * H_DIM];// k-split partials of dec_f
__device__ float  g_epart[8 * M_TOTAL];               // 8 N-tiles of 128 (compacted rows)
__device__ int    g_sidx[M_TOTAL];                    // compacted row -> original s
__device__ int    g_count[B_DIM];                     // unmasked count per batch
__device__ float  g_attnc[M_TOTAL];                   // compacted attention weights

#define SWZ(x) ((x) ^ (((x) >> 3) & 0x70))

// ---------------- K0: per-batch mask compaction (ordered scan) ----------------
__global__ void compact_kernel(const int* __restrict__ mask) {
    const int b = blockIdx.x, tid = threadIdx.x;
    const int lane = tid & 31, wid = tid >> 5;
    __shared__ int wsum[8];
    int m[8], loc[8];
    int t = 0;
    #pragma unroll
    for (int i = 0; i < 8; i++) {
        m[i] = mask[b * S_DIM + tid * 8 + i];
        loc[i] = t;
        t += (m[i] != 0);
    }
    int ws = t;
    #pragma unroll
    for (int off = 1; off < 32; off <<= 1) {
        int y = __shfl_up_sync(0xffffffffu, ws, off);
        if (lane >= off) ws += y;
    }
    if (lane == 31) wsum[wid] = ws;
    __syncthreads();
    if (wid == 0) {
        int v = (lane < 8) ? wsum[lane] : 0;
        #pragma unroll
        for (int off = 1; off < 8; off <<= 1) {
            int y = __shfl_up_sync(0xffffffffu, v, off);
            if (lane >= off) v += y;
        }
        if (lane < 8) wsum[lane] = v;
    }
    __syncthreads();
    int base = ws - t + ((wid > 0) ? wsum[wid - 1] : 0);
    #pragma unroll
    for (int i = 0; i < 8; i++)
        if (m[i]) g_sidx[b * S_DIM + base + loc[i]] = tid * 8 + i;
    if (tid == 255) g_count[b] = base + t;
}

// ---------------- K1: gather + fp32->fp16 convert of unmasked rows ----------------
__global__ void gather_kernel(const float* __restrict__ enc) {
    const int b = blockIdx.y, j = blockIdx.x, tid = threadIdx.x;
    const int cnt = g_count[b];
    const int cntP = (cnt + 63) & ~63;
    if (j >= cntP) return;
    __half2* dst = reinterpret_cast<__half2*>(g_enc16 + ((size_t)b * S_DIM + j) * E_DIM);
    if (j < cnt) {
        const int s = g_sidx[b * S_DIM + j];
        const float4* src = reinterpret_cast<const float4*>(enc) +
                            ((size_t)b * S_DIM + s) * (E_DIM / 4);
        #pragma unroll
        for (int i = 0; i < 2; i++) {
            float4 v = src[tid + i * 256];
            dst[2 * (tid + i * 256)]     = __floats2half2_rn(v.x, v.y);
            dst[2 * (tid + i * 256) + 1] = __floats2half2_rn(v.z, v.w);
        }
    } else {
        uint4 z = make_uint4(0, 0, 0, 0);
        reinterpret_cast<uint4*>(dst)[tid] = z;
    }
}

// ---------------- K2: W_s [k=2048][n=1024] -> g_wt[n][k] fp16 ----------------
__global__ void wt_kernel(const float* __restrict__ Ws) {
    __shared__ float t[32][33];
    int n0 = blockIdx.x * 32, k0 = blockIdx.y * 32;
    int tx = threadIdx.x, ty = threadIdx.y;  // 32 x 8
    #pragma unroll
    for (int i = 0; i < 32; i += 8)
        t[ty + i][tx] = Ws[(size_t)(k0 + ty + i) * H_DIM + n0 + tx];
    __syncthreads();
    #pragma unroll
    for (int i = 0; i < 32; i += 8)
        g_wt[(size_t)(n0 + ty + i) * E_DIM + k0 + tx] = __float2half(t[tx][ty + i]);
}

// ---------------- K3: dec_f partials, k-split x8 (deterministic, no atomics) -----
__global__ __launch_bounds__(256)
void decf_kernel(const float* __restrict__ dh, const float* __restrict__ Wh) {
    __shared__ float dsm[H_DIM / KSPLIT];            // 128 floats
    const int b = blockIdx.x >> 2;
    const int n = (blockIdx.x & 3) * 256 + threadIdx.x;
    const int ks = blockIdx.y;
    const int kbase = ks * (H_DIM / KSPLIT);
    if (threadIdx.x < H_DIM / KSPLIT)
        dsm[threadIdx.x] = dh[b * H_DIM + kbase + threadIdx.x];
    __syncthreads();
    float acc[8];
    #pragma unroll
    for (int j = 0; j < 8; j++) acc[j] = 0.f;
    #pragma unroll 2
    for (int k0 = 0; k0 < H_DIM / KSPLIT; k0 += 8) {
        #pragma unroll
        for (int j = 0; j < 8; j++)
            acc[j] = fmaf(dsm[k0 + j],
                          __ldg(&Wh[(size_t)(kbase + k0 + j) * H_DIM + n]), acc[j]);
    }
    float s = ((acc[0] + acc[1]) + (acc[2] + acc[3])) +
              ((acc[4] + acc[5]) + (acc[6] + acc[7]));
    g_decf_part[ks * (B_DIM * H_DIM) + b * H_DIM + n] = s;
}

// ---------------- K4: fused energy GEMM (2-stage, 4 CTAs/SM, reg-lean) ----------
// CTA: 128 threads (4 warps), tile M=64 x N=128, K chunks of 64.
// SWZ(r*128+d) = r*128 + (d ^ ((r&7)<<4)); r&7 invariant under 16-row strides
// -> affine address generation, ~44 fewer regs, fits 4 CTAs/SM (128 regs/thr).
static constexpr int STAGE_BYTES = 24576;
static constexpr int DYN_SMEM = 2 * STAGE_BYTES;     // 49152

__global__ __launch_bounds__(128, 4)
void energy_kernel(const float* __restrict__ v) {
    const int nTile = blockIdx.x & 7;
    const int mTile = blockIdx.x >> 3;
    const int row0 = mTile * 64;                 // = b*2048 + local
    const int b = mTile >> 5;
    const int local = row0 & (S_DIM - 1);
    if (local >= g_count[b]) return;             // compaction early exit

    extern __shared__ char dsm[];
    __shared__ float dec_sm[128], v_sm[128], e2[2][64];

    uint32_t sbase;
    asm("{ .reg .u64 t; cvta.to.shared.u64 t, %1; cvt.u32.u64 %0, t; }"
        : "=r"(sbase) : "l"(dsm));

    const int tid = threadIdx.x;
    const int lane = tid & 31, wid = tid >> 5;
    const int wm = wid & 1, wn = wid >> 1;       // warp tile: rows wm*32, cols wn*64
    const int n0 = nTile * 128;

    {   // dec_f = sum of KSPLIT partials (deterministic fixed order)
        float s = 0.f;
        #pragma unroll
        for (int ks = 0; ks < KSPLIT; ks++)
            s += g_decf_part[ks * (B_DIM * H_DIM) + b * H_DIM + n0 + tid];
        dec_sm[tid] = s;
    }
    v_sm[tid] = v[n0 + tid];

    const char* aG = reinterpret_cast<const char*>(g_enc16 + (size_t)row0 * E_DIM);
    const char* bG = reinterpret_cast<const char*>(g_wt + (size_t)n0 * E_DIM);

    // cp.async affine bases: r0 = tid>>3 (rows step 16/iter), c8 = tid&7
    const uint32_t cp_dst_base = ((uint32_t)(tid >> 3) * 128u) +
        (((uint32_t)(tid & 7) * 16u) ^ (((uint32_t)(tid >> 3) & 7u) << 4));
    const uint32_t cp_src_base = (uint32_t)(tid >> 3) * 4096u + (uint32_t)(tid & 7) * 16u;

    // ldmatrix: shared XOR'd column constants + per-fragment row bases
    uint32_t cxk[4];
    #pragma unroll
    for (int kk = 0; kk < 4; kk++)
        cxk[kk] = (uint32_t)((kk * 32 + ((lane >> 4) << 4)) ^ ((lane & 7) << 4));
    uint32_t rbA[2], rbB[4];
    #pragma unroll
    for (int mf = 0; mf < 2; mf++)
        rbA[mf] = (uint32_t)((wm * 32 + mf * 16 + (lane & 15)) * 128);
    #pragma unroll
    for (int ng = 0; ng < 4; ng++)
        rbB[ng] = 8192u + (uint32_t)((wn * 64 + ng * 16 + (lane & 15)) * 128);

    auto load_chunk = [&](int c, int s) {
        const uint32_t base = sbase + (uint32_t)s * STAGE_BYTES;
        const uint32_t koff = (uint32_t)c * 128u;
        const char* ga = aG + cp_src_base + koff;
        uint32_t da = base + cp_dst_base;
        #pragma unroll
        for (int it = 0; it < 4; ++it) {        // A: 64 rows x 8 x 16B
            asm volatile("cp.async.cg.shared.global [%0], [%1], 16;" :: "r"(da), "l"(ga));
            ga += 65536; da += 2048;
        }
        const char* gb = bG + cp_src_base + koff;
        uint32_t db = base + cp_dst_base + 8192u;
        #pragma unroll
        for (int it = 0; it < 8; ++it) {        // B: 128 rows x 8 x 16B
            asm volatile("cp.async.cg.shared.global [%0], [%1], 16;" :: "r"(db), "l"(gb));
            gb += 65536; db += 2048;
        }
        asm volatile("cp.async.commit_group;" ::: "memory");
    };

    float acc[2][8][4];
    #pragma unroll
    for (int i = 0; i < 2; i++)
        #pragma unroll
        for (int j = 0; j < 8; j++)
            #pragma unroll
            for (int q = 0; q < 4; q++) acc[i][j][q] = 0.f;

    load_chunk(0, 0);

    const int NC = E_DIM / 64;               // 32
    #pragma unroll 1
    for (int c = 0; c < NC; c++) {
        asm volatile("cp.async.wait_group 0;" ::: "memory");  // chunk c landed (self)
        // all threads' chunk c visible; every warp finished compute of c-1
        // -> stage (c+1)&1 == (c-1)&1 is free for the next load
        __syncthreads();
        if (c + 1 < NC) load_chunk(c + 1, (c + 1) & 1);

        const uint32_t stage = sbase + (uint32_t)(c & 1) * STAGE_BYTES;

        #pragma unroll
        for (int kk = 0; kk < 4; kk++) {
            uint32_t af[2][4], bf[4][4];
            #pragma unroll
            for (int mf = 0; mf < 2; mf++) {
                uint32_t a = stage + rbA[mf] + cxk[kk];
                asm volatile("ldmatrix.sync.aligned.m8n8.x4.shared.b16 {%0,%1,%2,%3}, [%4];"
                             : "=r"(af[mf][0]), "=r"(af[mf][1]), "=r"(af[mf][2]), "=r"(af[mf][3])
                             : "r"(a));
            }
            #pragma unroll
            for (int ng = 0; ng < 4; ng++) {
                uint32_t a = stage + rbB[ng] + cxk[kk];
                asm volatile("ldmatrix.sync.aligned.m8n8.x4.shared.b16 {%0,%1,%2,%3}, [%4];"
                             : "=r"(bf[ng][0]), "=r"(bf[ng][1]), "=r"(bf[ng][2]), "=r"(bf[ng][3])
                             : "r"(a));
            }
            #pragma unroll
            for (int mf = 0; mf < 2; mf++)
                #pragma unroll
                for (int nf = 0; nf < 8; nf++) {
                    int ng = nf >> 1, hi = nf & 1;
                    asm volatile(
                        "mma.sync.aligned.m16n8k16.row.col.f32.f16.f16.f32 "
                        "{%0,%1,%2,%3}, {%4,%5,%6,%7}, {%8,%9}, {%0,%1,%2,%3};"
                        : "+f"(acc[mf][nf][0]), "+f"(acc[mf][nf][1]),
                          "+f"(acc[mf][nf][2]), "+f"(acc[mf][nf][3])
                        : "r"(af[mf][0]), "r"(af[mf][1]), "r"(af[mf][2]), "r"(af[mf][3]),
                          "r"(bf[ng][hi]), "r"(bf[ng][hi + 2]));
                }
        }
    }

    // ---- epilogue: tanh + v-dot, per-warp reduce over its 64 cols ----
    float rsum[2][2];
    rsum[0][0] = rsum[0][1] = rsum[1][0] = rsum[1][1] = 0.f;
    #pragma unroll
    for (int mf = 0; mf < 2; mf++)
        #pragma unroll
        for (int nf = 0; nf < 8; nf++)
            #pragma unroll
            for (int rg = 0; rg < 4; rg++) {
                int col = wn * 64 + nf * 8 + (lane & 3) * 2 + (rg & 1);
                float x = acc[mf][nf][rg] + dec_sm[col];
                float ex = __expf(x + x);
                float th = 1.0f - __fdividef(2.0f, ex + 1.0f);
                rsum[mf][rg >> 1] = fmaf(th, v_sm[col], rsum[mf][rg >> 1]);
            }
    #pragma unroll
    for (int mf = 0; mf < 2; mf++)
        #pragma unroll
        for (int rh = 0; rh < 2; rh++) {
            float x = rsum[mf][rh];
            x += __shfl_xor_sync(0xffffffffu, x, 1);
            x += __shfl_xor_sync(0xffffffffu, x, 2);
            if ((lane & 3) == 0)
                e2[wn][wm * 32 + mf * 16 + rh * 8 + (lane >> 2)] = x;
        }
    __syncthreads();
    if (tid < 64)
        g_epart[(size_t)nTile * M_TOTAL + row0 + tid] = e2[0][tid] + e2[1][tid];
}

// ---------------- K5: softmax over compacted rows, scatter to attn ----------------
__global__ void softmax_kernel(float* __restrict__ out) {
    __shared__ float red[256];
    const int b = blockIdx.x, tid = threadIdx.x;
    const int cnt = g_count[b];
    float* attn = out + B_DIM * E_DIM;
    for (int j = tid; j < S_DIM; j += 256) attn[b * S_DIM + j] = 0.f;  // masked -> 0

    float e[8];
    float m = -1e30f;
    #pragma unroll
    for (int jj = 0; jj < 8; jj++) {
        int j = jj * 256 + tid;
        float x = -1e30f;
        if (j < cnt) {
            x = 0.f;
            #pragma unroll
            for (int t = 0; t < 8; t++)
                x += g_epart[(size_t)t * M_TOTAL + b * S_DIM + j];
        }
        e[jj] = x;
        m = fmaxf(m, x);
    }
    red[tid] = m; __syncthreads();
    for (int st = 128; st > 0; st >>= 1) {
        if (tid < st) red[tid] = fmaxf(red[tid], red[tid + st]);
        __syncthreads();
    }
    const float mx = red[0];
    __syncthreads();
    float sl = 0.f;
    #pragma unroll
    for (int jj = 0; jj < 8; jj++) {
        int j = jj * 256 + tid;
        float w = (j < cnt) ? __expf(e[jj] - mx) : 0.f;
        e[jj] = w;
        sl += w;
    }
    red[tid] = sl; __syncthreads();
    for (int st = 128; st > 0; st >>= 1) {
        if (tid < st) red[tid] += red[tid + st];
        __syncthreads();
    }
    const float inv = 1.0f / red[0];
    #pragma unroll
    for (int jj = 0; jj < 8; jj++) {
        int j = jj * 256 + tid;
        if (j < cnt) {
            float w = e[jj] * inv;
            attn[b * S_DIM + g_sidx[b * S_DIM + j]] = w;
            g_attnc[b * S_DIM + j] = w;
        }
    }
}

// ---------------- K6: context from compacted rows/weights ----------------
__global__ void context_kernel(float* __restrict__ out) {
    __shared__ float attn_sm[S_DIM];
    const int b = blockIdx.x >> 2;
    const int ec = blockIdx.x & 3;
    const int tid = threadIdx.x;
    const int cnt = g_count[b];
    const int cntP = (cnt + 63) & ~63;
    for (int i = tid; i < cntP; i += 256)
        attn_sm[i] = (i < cnt) ? g_attnc[b * S_DIM + i] : 0.f;
    __syncthreads();
    const int e0 = ec * 512 + tid * 2;
    const __half2* ep = reinterpret_cast<const __half2*>(
        g_enc16 + (size_t)b * S_DIM * E_DIM) + (e0 >> 1);
    float ax = 0.f, ay = 0.f;
    for (int s0 = 0; s0 < cntP; s0 += 8) {
        #pragma unroll
        for (int j = 0; j < 8; j++) {
            float2 f = __half22float2(ep[(size_t)(s0 + j) * (E_DIM / 2)]);
            float w = attn_sm[s0 + j];
            ax = fmaf(w, f.x, ax);
            ay = fmaf(w, f.y, ay);
        }
    }
    out[b * E_DIM + e0]     = ax;
    out[b * E_DIM + e0 + 1] = ay;
}

// ---------------- launch ----------------
extern "C" void kernel_launch(void* const* d_in, const int* in_sizes, int n_in,
                              void* d_out, int out_size) {
    const float* dh   = (const float*)d_in[0];
    const float* enc  = (const float*)d_in[1];
    const int*   mask = (const int*)d_in[2];
    const float* Wh   = (const float*)d_in[3];
    const float* Ws   = (const float*)d_in[4];
    const float* v    = (const float*)d_in[5];
    float* out = (float*)d_out;

    compact_kernel<<<B_DIM, 256>>>(mask);
    gather_kernel<<<dim3(S_DIM, B_DIM), 256>>>(enc);
    wt_kernel<<<dim3(32, 64), dim3(32, 8)>>>(Ws);
    decf_kernel<<<dim3(256, KSPLIT), 256>>>(dh, Wh);

    cudaFuncSetAttribute(energy_kernel, cudaFuncAttributeMaxDynamicSharedMemorySize, DYN_SMEM);
    energy_kernel<<<16384, 128, DYN_SMEM>>>(v);

    softmax_kernel<<<64, 256>>>(out);
    context_kernel<<<256, 256>>>(out);
}